// round 4
// baseline (speedup 1.0000x reference)
#include <cuda_runtime.h>
#include <cuda_bf16.h>
#include <stdint.h>
#include <math.h>

#define NB 8
#define NC 64
#define TI 128          // i-tile (8 warps x 16)
#define TJ 64           // j-tile
#define NN 4000
#define JT_MAX 63       // ceil(4000/64)
#define SMSTRIDE 72     // 64 bf16 + 8 pad

// Scratch (device globals; no allocations allowed)
__device__ __nv_bfloat16 g_featn[NB * NN * NC];
__device__ int           g_ridN[NB * NN];
__device__ int           g_ridA[NB * NN];
__device__ int           g_cnt[NB];
__device__ double        g_pos[NB];
__device__ double        g_neg[NB];

// ---------------------------------------------------------------------------
// Kernel 1: row-normalize (fp32 math) -> bf16 [b][n][c]
// ---------------------------------------------------------------------------
__global__ void normalize_kernel(const float* __restrict__ feat) {
    int row = blockIdx.x * blockDim.x + threadIdx.x;
    if (row >= NB * NN) return;
    int b = row / NN;
    int n = row - b * NN;
    const float* src = feat + (size_t)b * NC * NN + n;
    float v[NC];
    float ss = 0.f;
#pragma unroll
    for (int c = 0; c < NC; c++) {
        float x = src[(size_t)c * NN];
        v[c] = x;
        ss += x * x;
    }
    float inv = 1.0f / fmaxf(sqrtf(ss), 1e-12f);
    __nv_bfloat16* dst = g_featn + (size_t)row * NC;
#pragma unroll
    for (int c = 0; c < NC; c++) dst[c] = __float2bfloat16(v[c] * inv);
}

// ---------------------------------------------------------------------------
// Kernel 2: compact normal + anomaly lists per batch (deterministic)
// ---------------------------------------------------------------------------
__global__ void compact_kernel(const float* __restrict__ prob) {
    int b = blockIdx.x;
    int tid = threadIdx.x;
    __shared__ int wtN[8], wtA[8];
    __shared__ int baseN, baseA;
    if (tid == 0) { baseN = 0; baseA = 0; }
    __syncthreads();

    for (int c0 = 0; c0 < NN; c0 += 256) {
        int idx = c0 + tid;
        bool inr = idx < NN;
        bool nrm = false;
        if (inr) nrm = prob[b * NN + idx] < 0.5f;
        bool ano = inr && !nrm;
        unsigned mN = __ballot_sync(0xffffffffu, nrm);
        unsigned mA = __ballot_sync(0xffffffffu, ano);
        int lane = tid & 31, wid = tid >> 5;
        unsigned below = (1u << lane) - 1u;
        int pN = __popc(mN & below), pA = __popc(mA & below);
        if (lane == 0) { wtN[wid] = __popc(mN); wtA[wid] = __popc(mA); }
        __syncthreads();
        int oN = 0, oA = 0, tN = 0, tA = 0;
        for (int w = 0; w < 8; w++) {
            if (w < wid) { oN += wtN[w]; oA += wtA[w]; }
            tN += wtN[w]; tA += wtA[w];
        }
        if (nrm) g_ridN[b * NN + baseN + oN + pN] = idx;
        if (ano) g_ridA[b * NN + baseA + oA + pA] = idx;
        __syncthreads();
        if (tid == 0) { baseN += tN; baseA += tA; }
        __syncthreads();
    }
    if (tid == 0) {
        g_cnt[b] = baseN;
        g_pos[b] = 0.0;
        g_neg[b] = 0.0;
    }
}

// ---------------------------------------------------------------------------
// Merged tensor-core fused GEMM + loss. mode 0: normal x normal (skip diag,
// exp-sum); mode 1: normal x anomaly (softplus-style neg term).
// Block: 256 thr = 8 warps stacked along M (warp tile 16x64). Tile 128x64.
// ---------------------------------------------------------------------------
__device__ __forceinline__ void ldm_x4(unsigned r[4], unsigned addr) {
    asm volatile("ldmatrix.sync.aligned.m8n8.x4.shared.b16 {%0,%1,%2,%3}, [%4];\n"
                 : "=r"(r[0]), "=r"(r[1]), "=r"(r[2]), "=r"(r[3]) : "r"(addr));
}
__device__ __forceinline__ void mma_bf16(float d[4], const unsigned a[4],
                                         const unsigned b2[2]) {
    asm volatile(
        "mma.sync.aligned.m16n8k16.row.col.f32.bf16.bf16.f32 "
        "{%0,%1,%2,%3}, {%4,%5,%6,%7}, {%8,%9}, {%0,%1,%2,%3};\n"
        : "+f"(d[0]), "+f"(d[1]), "+f"(d[2]), "+f"(d[3])
        : "r"(a[0]), "r"(a[1]), "r"(a[2]), "r"(a[3]), "r"(b2[0]), "r"(b2[1]));
}

__global__ __launch_bounds__(256, 3) void mma_loss_kernel() {
    int b = blockIdx.z;
    int nI = g_cnt[b];
    int mode = (blockIdx.x >= JT_MAX) ? 1 : 0;
    int jt = blockIdx.x - mode * JT_MAX;
    int nJ = mode ? (NN - nI) : nI;
    int i0 = blockIdx.y * TI;
    int j0 = jt * TJ;
    if (i0 >= nI || j0 >= nJ) return;

    __shared__ __nv_bfloat16 As[TI][SMSTRIDE];
    __shared__ __nv_bfloat16 Bs[TJ][SMSTRIDE];
    __shared__ float s_warp[8];

    int tid = threadIdx.x;
    const int* ridI = g_ridN + b * NN;
    const int* ridJ = mode ? (g_ridA + b * NN) : (g_ridN + b * NN);
    const __nv_bfloat16* fb = g_featn + (size_t)b * NN * NC;

    // Cooperative tile gather: A rows 0..127, B rows 0..63; 8 uint4 per row.
    for (int t = tid; t < TI * 8; t += 256) {
        int r = t >> 3, c = t & 7;
        uint4 v = make_uint4(0, 0, 0, 0);
        int gi = i0 + r;
        if (gi < nI) v = ((const uint4*)(fb + (size_t)ridI[gi] * NC))[c];
        *(uint4*)&As[r][c * 8] = v;
    }
    for (int t = tid; t < TJ * 8; t += 256) {
        int r = t >> 3, c = t & 7;
        uint4 w = make_uint4(0, 0, 0, 0);
        int gj = j0 + r;
        if (gj < nJ) w = ((const uint4*)(fb + (size_t)ridJ[gj] * NC))[c];
        *(uint4*)&Bs[r][c * 8] = w;
    }
    __syncthreads();

    int warp = tid >> 5, lane = tid & 31;
    int mBase = warp * 16;                 // warp tile 16 (M) x 64 (N)

    float acc[8][4];
#pragma unroll
    for (int ni = 0; ni < 8; ni++)
#pragma unroll
        for (int e = 0; e < 4; e++) acc[ni][e] = 0.f;

#pragma unroll
    for (int ks = 0; ks < 4; ks++) {
        int k0 = ks * 16;
        unsigned afr[4];
        {
            unsigned a = (unsigned)__cvta_generic_to_shared(
                &As[mBase + (lane & 15)][k0 + (lane >> 4) * 8]);
            ldm_x4(afr, a);
        }
        unsigned bfr[8][2];
#pragma unroll
        for (int np = 0; np < 4; np++) {
            unsigned bt[4];
            unsigned a = (unsigned)__cvta_generic_to_shared(
                &Bs[np * 16 + (lane & 7) + 8 * (lane >> 4)]
                   [k0 + ((lane >> 3) & 1) * 8]);
            ldm_x4(bt, a);
            bfr[np * 2 + 0][0] = bt[0]; bfr[np * 2 + 0][1] = bt[1];
            bfr[np * 2 + 1][0] = bt[2]; bfr[np * 2 + 1][1] = bt[3];
        }
#pragma unroll
        for (int ni = 0; ni < 8; ni++)
            mma_bf16(acc[ni], afr, bfr[ni]);
    }

    // Fused epilogue. sim = dot * 10; exp(sim) = exp2(dot * 10*log2(e)).
    const float K10LOG2E = 14.4269504089f;   // 10 / ln(2)
    int g = lane >> 2, tq = lane & 3;
    int riBase = i0 + mBase + g;
    int cjBase = j0 + tq * 2;
    float sumv = 0.f;
#pragma unroll
    for (int ni = 0; ni < 8; ni++) {
#pragma unroll
        for (int e = 0; e < 4; e++) {
            int ri = riBase + ((e >> 1) ? 8 : 0);
            int cj = cjBase + ni * 8 + (e & 1);
            if (ri >= nI || cj >= nJ) continue;
            float ex = exp2f(acc[ni][e] * K10LOG2E);
            if (mode == 0) {
                if (ri != cj) sumv += ex;          // diag = equal compact idx
            } else {
                float u = __fdividef(1.0f, 1.0f + ex);  // 1 - sigmoid(sim)
                sumv -= __logf(u + 1e-6f);
            }
        }
    }

    // Warp reduce -> smem -> warp0 reduce -> one double atomic.
#pragma unroll
    for (int o = 16; o; o >>= 1)
        sumv += __shfl_down_sync(0xffffffffu, sumv, o);
    if (lane == 0) s_warp[warp] = sumv;
    __syncthreads();
    if (warp == 0) {
        float v = (lane < 8) ? s_warp[lane] : 0.f;
#pragma unroll
        for (int o = 4; o; o >>= 1)
            v += __shfl_down_sync(0xffffffffu, v, o);
        if (lane == 0) {
            if (mode == 0) atomicAdd(&g_pos[b], (double)v);
            else           atomicAdd(&g_neg[b], (double)v);
        }
    }
}

// ---------------------------------------------------------------------------
// Finalize scalar
// ---------------------------------------------------------------------------
__global__ void finalize_kernel(float* __restrict__ out) {
    int tid = threadIdx.x;
    double per = 0.0, vcnt = 0.0;
    if (tid < NB) {
        int nn = g_cnt[tid];
        int na = NN - nn;
        bool valid = (nn >= 10) && (na >= 5);
        double pc = (double)nn * (double)nn - (double)nn;
        double cc = (double)nn * (double)na;
        double pm = g_pos[tid] / (pc > 1.0 ? pc : 1.0);
        double pl = -log(pm + 1e-6);
        double nl = g_neg[tid] / (cc > 1.0 ? cc : 1.0);
        if (valid) { per = pl + nl; vcnt = 1.0; }
    }
    for (int o = 16; o; o >>= 1) {
        per += __shfl_down_sync(0xffffffffu, per, o);
        vcnt += __shfl_down_sync(0xffffffffu, vcnt, o);
    }
    if (tid == 0) out[0] = (float)(per / (vcnt > 1.0 ? vcnt : 1.0));
}

extern "C" void kernel_launch(void* const* d_in, const int* in_sizes, int n_in,
                              void* d_out, int out_size) {
    const float* feat = (const float*)d_in[0];   // [8,64,4000,1]
    const float* prob = (const float*)d_in[1];   // [8,1,4000,1]

    normalize_kernel<<<(NB * NN + 255) / 256, 256>>>(feat);
    compact_kernel<<<NB, 256>>>(prob);
    dim3 grid(2 * JT_MAX, (NN + TI - 1) / TI, NB);   // (mode|jt, it, b)
    mma_loss_kernel<<<grid, 256>>>();
    finalize_kernel<<<1, 32>>>((float*)d_out);
}

// round 5
// speedup vs baseline: 1.1162x; 1.1162x over previous
#include <cuda_runtime.h>
#include <cuda_bf16.h>
#include <stdint.h>
#include <math.h>

#define NB 8
#define NC 64
#define NN 4000
#define TILE 128
#define JT_MAX 32       // ceil(4000/128)
#define SMSTRIDE 72     // 64 bf16 + 8 pad -> ldmatrix conflict-free

// Scratch (device globals; no allocations allowed)
__device__ __nv_bfloat16 g_featn[NB * NN * NC];
__device__ int           g_ridN[NB * NN];
__device__ int           g_ridA[NB * NN];
__device__ int           g_cnt[NB];
__device__ double        g_pos[NB];
__device__ double        g_neg[NB];

// ---------------------------------------------------------------------------
// Kernel 1: row-normalize (fp32 math) -> bf16 [b][n][c]
// ---------------------------------------------------------------------------
__global__ void normalize_kernel(const float* __restrict__ feat) {
    int row = blockIdx.x * blockDim.x + threadIdx.x;
    if (row >= NB * NN) return;
    int b = row / NN;
    int n = row - b * NN;
    const float* src = feat + (size_t)b * NC * NN + n;
    float v[NC];
    float ss = 0.f;
#pragma unroll
    for (int c = 0; c < NC; c++) {
        float x = src[(size_t)c * NN];
        v[c] = x;
        ss += x * x;
    }
    float inv = 1.0f / fmaxf(sqrtf(ss), 1e-12f);
    __nv_bfloat16* dst = g_featn + (size_t)row * NC;
#pragma unroll
    for (int c = 0; c < NC; c++) dst[c] = __float2bfloat16(v[c] * inv);
}

// ---------------------------------------------------------------------------
// Kernel 2: compact normal + anomaly lists per batch (deterministic)
// ---------------------------------------------------------------------------
__global__ void compact_kernel(const float* __restrict__ prob) {
    int b = blockIdx.x;
    int tid = threadIdx.x;
    __shared__ int wtN[8], wtA[8];
    __shared__ int baseN, baseA;
    if (tid == 0) { baseN = 0; baseA = 0; }
    __syncthreads();

    for (int c0 = 0; c0 < NN; c0 += 256) {
        int idx = c0 + tid;
        bool inr = idx < NN;
        bool nrm = false;
        if (inr) nrm = prob[b * NN + idx] < 0.5f;
        bool ano = inr && !nrm;
        unsigned mN = __ballot_sync(0xffffffffu, nrm);
        unsigned mA = __ballot_sync(0xffffffffu, ano);
        int lane = tid & 31, wid = tid >> 5;
        unsigned below = (1u << lane) - 1u;
        int pN = __popc(mN & below), pA = __popc(mA & below);
        if (lane == 0) { wtN[wid] = __popc(mN); wtA[wid] = __popc(mA); }
        __syncthreads();
        int oN = 0, oA = 0, tN = 0, tA = 0;
        for (int w = 0; w < 8; w++) {
            if (w < wid) { oN += wtN[w]; oA += wtA[w]; }
            tN += wtN[w]; tA += wtA[w];
        }
        if (nrm) g_ridN[b * NN + baseN + oN + pN] = idx;
        if (ano) g_ridA[b * NN + baseA + oA + pA] = idx;
        __syncthreads();
        if (tid == 0) { baseN += tN; baseA += tA; }
        __syncthreads();
    }
    if (tid == 0) {
        g_cnt[b] = baseN;
        g_pos[b] = 0.0;
        g_neg[b] = 0.0;
    }
}

// ---------------------------------------------------------------------------
// Merged tensor-core fused GEMM + loss. mode 0: normal x normal (skip diag,
// sum exp); mode 1: normal x anomaly (softplus). Tile 128x128, 8 warps (4x2),
// warp tile 32x64, mma.sync m16n8k16 bf16 -> fp32, full K=64 in smem.
// ---------------------------------------------------------------------------
__device__ __forceinline__ void ldm_x4(unsigned r[4], unsigned addr) {
    asm volatile("ldmatrix.sync.aligned.m8n8.x4.shared.b16 {%0,%1,%2,%3}, [%4];\n"
                 : "=r"(r[0]), "=r"(r[1]), "=r"(r[2]), "=r"(r[3]) : "r"(addr));
}
__device__ __forceinline__ void mma_bf16(float d[4], const unsigned a[4],
                                         const unsigned b2[2]) {
    asm volatile(
        "mma.sync.aligned.m16n8k16.row.col.f32.bf16.bf16.f32 "
        "{%0,%1,%2,%3}, {%4,%5,%6,%7}, {%8,%9}, {%0,%1,%2,%3};\n"
        : "+f"(d[0]), "+f"(d[1]), "+f"(d[2]), "+f"(d[3])
        : "r"(a[0]), "r"(a[1]), "r"(a[2]), "r"(a[3]), "r"(b2[0]), "r"(b2[1]));
}

__global__ __launch_bounds__(256, 2) void mma_loss_kernel() {
    int b = blockIdx.z;
    int nI = g_cnt[b];
    int mode = (blockIdx.x >= JT_MAX) ? 1 : 0;
    int jt = blockIdx.x - mode * JT_MAX;
    int nJ = mode ? (NN - nI) : nI;
    int i0 = blockIdx.y * TILE;
    int j0 = jt * TILE;
    if (i0 >= nI || j0 >= nJ) return;

    __shared__ __nv_bfloat16 As[TILE][SMSTRIDE];
    __shared__ __nv_bfloat16 Bs[TILE][SMSTRIDE];
    __shared__ float s_warp[8];

    int tid = threadIdx.x;
    const int* ridI = g_ridN + b * NN;
    const int* ridJ = mode ? (g_ridA + b * NN) : (g_ridN + b * NN);
    const __nv_bfloat16* fb = g_featn + (size_t)b * NN * NC;

    // Cooperative tile gather: 8 uint4 per 128B row; zero-pad OOB rows.
    for (int t = tid; t < TILE * 8; t += 256) {
        int r = t >> 3, c = t & 7;
        uint4 v = make_uint4(0, 0, 0, 0);
        int gi = i0 + r;
        if (gi < nI) v = ((const uint4*)(fb + (size_t)ridI[gi] * NC))[c];
        *(uint4*)&As[r][c * 8] = v;
        uint4 w = make_uint4(0, 0, 0, 0);
        int gj = j0 + r;
        if (gj < nJ) w = ((const uint4*)(fb + (size_t)ridJ[gj] * NC))[c];
        *(uint4*)&Bs[r][c * 8] = w;
    }
    __syncthreads();

    int warp = tid >> 5, lane = tid & 31;
    int wm = warp >> 1, wn = warp & 1;      // 4 (M) x 2 (N) warps
    int mBase = wm * 32, nBase = wn * 64;   // warp tile 32 x 64

    float acc[2][8][4];
#pragma unroll
    for (int mi = 0; mi < 2; mi++)
#pragma unroll
        for (int ni = 0; ni < 8; ni++)
#pragma unroll
            for (int e = 0; e < 4; e++) acc[mi][ni][e] = 0.f;

#pragma unroll
    for (int ks = 0; ks < 4; ks++) {
        int k0 = ks * 16;
        unsigned afr[2][4];
#pragma unroll
        for (int mi = 0; mi < 2; mi++) {
            unsigned a = (unsigned)__cvta_generic_to_shared(
                &As[mBase + mi * 16 + (lane & 15)][k0 + (lane >> 4) * 8]);
            ldm_x4(afr[mi], a);
        }
        unsigned bfr[8][2];
#pragma unroll
        for (int np = 0; np < 4; np++) {
            unsigned bt[4];
            unsigned a = (unsigned)__cvta_generic_to_shared(
                &Bs[nBase + np * 16 + (lane & 7) + 8 * (lane >> 4)]
                   [k0 + ((lane >> 3) & 1) * 8]);
            ldm_x4(bt, a);
            bfr[np * 2 + 0][0] = bt[0]; bfr[np * 2 + 0][1] = bt[1];
            bfr[np * 2 + 1][0] = bt[2]; bfr[np * 2 + 1][1] = bt[3];
        }
#pragma unroll
        for (int mi = 0; mi < 2; mi++)
#pragma unroll
            for (int ni = 0; ni < 8; ni++)
                mma_bf16(acc[mi][ni], afr[mi], bfr[ni]);
    }

    // Fused epilogue. sim = dot*10; exp(sim) = exp2(dot * 10*log2e).
    // mode 0: sum exp(sim) over off-diagonal.
    // mode 1: sum log2(1 + exp(sim)); multiply by ln2 once at the end.
    //   (-log(1-sigmoid(s)+eps) = log(1+e^s) - log(1+eps(1+e^s));
    //    the eps correction is ~3e-6 relative — dropped.)
    const float K10LOG2E = 14.4269504089f;   // 10 * log2(e)
    int g = lane >> 2, tq = lane & 3;
    float sumv = 0.f;
#pragma unroll
    for (int mi = 0; mi < 2; mi++) {
#pragma unroll
        for (int ni = 0; ni < 8; ni++) {
#pragma unroll
            for (int e = 0; e < 4; e++) {
                int ri = i0 + mBase + mi * 16 + g + ((e >> 1) ? 8 : 0);
                int cj = j0 + nBase + ni * 8 + tq * 2 + (e & 1);
                if (ri >= nI || cj >= nJ) continue;
                float ex = exp2f(acc[mi][ni][e] * K10LOG2E);
                if (mode == 0) {
                    if (ri != cj) sumv += ex;      // diag = equal compact idx
                } else {
                    sumv += __log2f(1.0f + ex);    // softplus / ln2
                }
            }
        }
    }

    // Warp reduce -> smem -> warp0 reduce -> one double atomic per block.
#pragma unroll
    for (int o = 16; o; o >>= 1)
        sumv += __shfl_down_sync(0xffffffffu, sumv, o);
    if (lane == 0) s_warp[warp] = sumv;
    __syncthreads();
    if (warp == 0) {
        float v = (lane < 8) ? s_warp[lane] : 0.f;
#pragma unroll
        for (int o = 4; o; o >>= 1)
            v += __shfl_down_sync(0xffffffffu, v, o);
        if (lane == 0) {
            if (mode == 0) atomicAdd(&g_pos[b], (double)v);
            else atomicAdd(&g_neg[b], (double)v * 0.6931471805599453);  // ln2
        }
    }
}

// ---------------------------------------------------------------------------
// Finalize scalar
// ---------------------------------------------------------------------------
__global__ void finalize_kernel(float* __restrict__ out) {
    int tid = threadIdx.x;
    double per = 0.0, vcnt = 0.0;
    if (tid < NB) {
        int nn = g_cnt[tid];
        int na = NN - nn;
        bool valid = (nn >= 10) && (na >= 5);
        double pc = (double)nn * (double)nn - (double)nn;
        double cc = (double)nn * (double)na;
        double pm = g_pos[tid] / (pc > 1.0 ? pc : 1.0);
        double pl = -log(pm + 1e-6);
        double nl = g_neg[tid] / (cc > 1.0 ? cc : 1.0);
        if (valid) { per = pl + nl; vcnt = 1.0; }
    }
    for (int o = 16; o; o >>= 1) {
        per += __shfl_down_sync(0xffffffffu, per, o);
        vcnt += __shfl_down_sync(0xffffffffu, vcnt, o);
    }
    if (tid == 0) out[0] = (float)(per / (vcnt > 1.0 ? vcnt : 1.0));
}

extern "C" void kernel_launch(void* const* d_in, const int* in_sizes, int n_in,
                              void* d_out, int out_size) {
    const float* feat = (const float*)d_in[0];   // [8,64,4000,1]
    const float* prob = (const float*)d_in[1];   // [8,1,4000,1]

    normalize_kernel<<<(NB * NN + 255) / 256, 256>>>(feat);
    compact_kernel<<<NB, 256>>>(prob);
    dim3 grid(2 * JT_MAX, (NN + TILE - 1) / TILE, NB);   // (mode|jt, it, b)
    mma_loss_kernel<<<grid, 256>>>();
    finalize_kernel<<<1, 32>>>((float*)d_out);
}

// round 6
// speedup vs baseline: 1.2969x; 1.1619x over previous
#include <cuda_runtime.h>
#include <cuda_bf16.h>
#include <stdint.h>
#include <math.h>

#define NB 8
#define NC 64
#define NN 4000
#define TI 128          // i-tile
#define TJ 64           // j-tile
#define JT63 63         // ceil(4000/64) j-tiles per mode
#define SMSTRIDE 72     // 64 bf16 + 8 pad (144B rows; 16B-aligned; ldmatrix conflict-free)

// Scratch (device globals; no allocations allowed)
__device__ __nv_bfloat16 g_feat2[NB * NN * NC];  // normalized, COMPACTED order:
                                                 // rows [0,nI) normal, [nI,NN) anomaly
__device__ int           g_pmap[NB * NN];        // orig idx -> p (normal) or ~pA (anomaly)
__device__ int           g_cnt[NB];
__device__ double        g_pos[NB];
__device__ double        g_neg[NB];

// ---------------------------------------------------------------------------
// Kernel 1: classify + build position map (deterministic), init accumulators.
// ---------------------------------------------------------------------------
__global__ void compact_kernel(const float* __restrict__ prob) {
    int b = blockIdx.x;
    int tid = threadIdx.x;
    __shared__ int wtN[8], wtA[8];
    __shared__ int baseN, baseA;
    if (tid == 0) { baseN = 0; baseA = 0; }
    __syncthreads();

    for (int c0 = 0; c0 < NN; c0 += 256) {
        int idx = c0 + tid;
        bool inr = idx < NN;
        bool nrm = false;
        if (inr) nrm = prob[b * NN + idx] < 0.5f;
        bool ano = inr && !nrm;
        unsigned mN = __ballot_sync(0xffffffffu, nrm);
        unsigned mA = __ballot_sync(0xffffffffu, ano);
        int lane = tid & 31, wid = tid >> 5;
        unsigned below = (1u << lane) - 1u;
        int pN = __popc(mN & below), pA = __popc(mA & below);
        if (lane == 0) { wtN[wid] = __popc(mN); wtA[wid] = __popc(mA); }
        __syncthreads();
        int oN = 0, oA = 0, tN = 0, tA = 0;
        for (int w = 0; w < 8; w++) {
            if (w < wid) { oN += wtN[w]; oA += wtA[w]; }
            tN += wtN[w]; tA += wtA[w];
        }
        if (nrm) g_pmap[b * NN + idx] = baseN + oN + pN;
        if (ano) g_pmap[b * NN + idx] = ~(baseA + oA + pA);
        __syncthreads();
        if (tid == 0) { baseN += tN; baseA += tA; }
        __syncthreads();
    }
    if (tid == 0) {
        g_cnt[b] = baseN;
        g_pos[b] = 0.0;
        g_neg[b] = 0.0;
    }
}

// ---------------------------------------------------------------------------
// Kernel 2: row-normalize (fp32) -> bf16, writing to COMPACTED row position.
// Reads coalesced (consecutive n per fixed c); writes 128B rows scattered.
// ---------------------------------------------------------------------------
__global__ void normalize_kernel(const float* __restrict__ feat) {
    int row = blockIdx.x * blockDim.x + threadIdx.x;
    if (row >= NB * NN) return;
    int b = row / NN;
    int n = row - b * NN;
    const float* src = feat + (size_t)b * NC * NN + n;
    float v[NC];
    float ss = 0.f;
#pragma unroll
    for (int c = 0; c < NC; c++) {
        float x = src[(size_t)c * NN];
        v[c] = x;
        ss += x * x;
    }
    float inv = 1.0f / fmaxf(sqrtf(ss), 1e-12f);
    int pm = g_pmap[b * NN + n];
    int dstRow = (pm >= 0) ? pm : (g_cnt[b] + ~pm);
    __nv_bfloat16* dst = g_feat2 + ((size_t)b * NN + dstRow) * NC;
#pragma unroll
    for (int c = 0; c < NC; c++) dst[c] = __float2bfloat16(v[c] * inv);
}

// ---------------------------------------------------------------------------
// Merged fused GEMM + loss. mode 0: normal x normal (skip diag, sum exp);
// mode 1: normal x anomaly (softplus). Tile 128x64, 8 warps stacked in M,
// warp tile 16x64 (acc = 32 regs). Contiguous cp.async tile fills.
// ---------------------------------------------------------------------------
__device__ __forceinline__ void cpa16(unsigned dst, const void* src, bool valid) {
    int sz = valid ? 16 : 0;
    asm volatile("cp.async.cg.shared.global [%0], [%1], 16, %2;\n"
                 :: "r"(dst), "l"(src), "r"(sz));
}
__device__ __forceinline__ void ldm_x4(unsigned r[4], unsigned addr) {
    asm volatile("ldmatrix.sync.aligned.m8n8.x4.shared.b16 {%0,%1,%2,%3}, [%4];\n"
                 : "=r"(r[0]), "=r"(r[1]), "=r"(r[2]), "=r"(r[3]) : "r"(addr));
}
__device__ __forceinline__ void mma_bf16(float d[4], const unsigned a[4],
                                         unsigned b0, unsigned b1) {
    asm volatile(
        "mma.sync.aligned.m16n8k16.row.col.f32.bf16.bf16.f32 "
        "{%0,%1,%2,%3}, {%4,%5,%6,%7}, {%8,%9}, {%0,%1,%2,%3};\n"
        : "+f"(d[0]), "+f"(d[1]), "+f"(d[2]), "+f"(d[3])
        : "r"(a[0]), "r"(a[1]), "r"(a[2]), "r"(a[3]), "r"(b0), "r"(b1));
}

__global__ __launch_bounds__(256, 3) void mma_loss_kernel() {
    int b = blockIdx.z;
    int nI = g_cnt[b];
    int mode = (blockIdx.x >= JT63) ? 1 : 0;
    int jt = blockIdx.x - mode * JT63;
    int nJ = mode ? (NN - nI) : nI;
    int i0 = blockIdx.y * TI;
    int j0 = jt * TJ;
    if (i0 >= nI || j0 >= nJ) return;

    __shared__ __nv_bfloat16 As[TI][SMSTRIDE];
    __shared__ __nv_bfloat16 Bs[TJ][SMSTRIDE];
    __shared__ float s_warp[8];

    int tid = threadIdx.x;
    const __nv_bfloat16* Abase = g_feat2 + ((size_t)b * NN + i0) * NC;
    const __nv_bfloat16* Bbase =
        g_feat2 + ((size_t)b * NN + (mode ? nI : 0) + j0) * NC;

    // cp.async tile fills: A = 1024 16B chunks (4/thread), B = 512 (2/thread).
#pragma unroll
    for (int c = 0; c < 4; c++) {
        int chunk = tid + c * 256;
        int r = chunk >> 3, col = chunk & 7;
        unsigned dst = (unsigned)__cvta_generic_to_shared(&As[r][col * 8]);
        cpa16(dst, Abase + (size_t)r * NC + col * 8, (i0 + r) < nI);
    }
#pragma unroll
    for (int c = 0; c < 2; c++) {
        int chunk = tid + c * 256;
        int r = chunk >> 3, col = chunk & 7;
        unsigned dst = (unsigned)__cvta_generic_to_shared(&Bs[r][col * 8]);
        cpa16(dst, Bbase + (size_t)r * NC + col * 8, (j0 + r) < nJ);
    }
    asm volatile("cp.async.commit_group;\n");
    asm volatile("cp.async.wait_group 0;\n");
    __syncthreads();

    int warp = tid >> 5, lane = tid & 31;
    int mBase = warp * 16;               // warp tile 16 (M) x 64 (N)

    float acc[8][4];
#pragma unroll
    for (int ni = 0; ni < 8; ni++)
#pragma unroll
        for (int e = 0; e < 4; e++) acc[ni][e] = 0.f;

#pragma unroll
    for (int ks = 0; ks < 4; ks++) {
        int k0 = ks * 16;
        unsigned afr[4];
        {
            unsigned a = (unsigned)__cvta_generic_to_shared(
                &As[mBase + (lane & 15)][k0 + (lane >> 4) * 8]);
            ldm_x4(afr, a);
        }
#pragma unroll
        for (int np = 0; np < 4; np++) {
            unsigned bt[4];
            unsigned a = (unsigned)__cvta_generic_to_shared(
                &Bs[np * 16 + (lane & 7) + 8 * (lane >> 4)]
                   [k0 + ((lane >> 3) & 1) * 8]);
            ldm_x4(bt, a);
            mma_bf16(acc[np * 2 + 0], afr, bt[0], bt[1]);
            mma_bf16(acc[np * 2 + 1], afr, bt[2], bt[3]);
        }
    }

    // Fused epilogue. sim = dot*10; exp(sim) = exp2(dot*10*log2e).
    // mode 0: sum exp(sim), skip diag (equal compact index).
    // mode 1: sum log2(1+exp(sim)); * ln2 once at the end (eps ~3e-6 rel, dropped).
    const float K10LOG2E = 14.4269504089f;
    int g = lane >> 2, tq = lane & 3;
    int riB = i0 + mBase + g;
    int cjB = j0 + tq * 2;
    float sumv = 0.f;
#pragma unroll
    for (int ni = 0; ni < 8; ni++) {
#pragma unroll
        for (int e = 0; e < 4; e++) {
            int ri = riB + ((e >> 1) ? 8 : 0);
            int cj = cjB + ni * 8 + (e & 1);
            if (ri >= nI || cj >= nJ) continue;
            float ex = exp2f(acc[ni][e] * K10LOG2E);
            if (mode == 0) {
                if (ri != cj) sumv += ex;
            } else {
                sumv += __log2f(1.0f + ex);
            }
        }
    }

#pragma unroll
    for (int o = 16; o; o >>= 1)
        sumv += __shfl_down_sync(0xffffffffu, sumv, o);
    if (lane == 0) s_warp[warp] = sumv;
    __syncthreads();
    if (warp == 0) {
        float v = (lane < 8) ? s_warp[lane] : 0.f;
#pragma unroll
        for (int o = 4; o; o >>= 1)
            v += __shfl_down_sync(0xffffffffu, v, o);
        if (lane == 0) {
            if (mode == 0) atomicAdd(&g_pos[b], (double)v);
            else atomicAdd(&g_neg[b], (double)v * 0.6931471805599453);  // ln2
        }
    }
}

// ---------------------------------------------------------------------------
// Finalize scalar
// ---------------------------------------------------------------------------
__global__ void finalize_kernel(float* __restrict__ out) {
    int tid = threadIdx.x;
    double per = 0.0, vcnt = 0.0;
    if (tid < NB) {
        int nn = g_cnt[tid];
        int na = NN - nn;
        bool valid = (nn >= 10) && (na >= 5);
        double pc = (double)nn * (double)nn - (double)nn;
        double cc = (double)nn * (double)na;
        double pm = g_pos[tid] / (pc > 1.0 ? pc : 1.0);
        double pl = -log(pm + 1e-6);
        double nl = g_neg[tid] / (cc > 1.0 ? cc : 1.0);
        if (valid) { per = pl + nl; vcnt = 1.0; }
    }
    for (int o = 16; o; o >>= 1) {
        per += __shfl_down_sync(0xffffffffu, per, o);
        vcnt += __shfl_down_sync(0xffffffffu, vcnt, o);
    }
    if (tid == 0) out[0] = (float)(per / (vcnt > 1.0 ? vcnt : 1.0));
}

extern "C" void kernel_launch(void* const* d_in, const int* in_sizes, int n_in,
                              void* d_out, int out_size) {
    const float* feat = (const float*)d_in[0];   // [8,64,4000,1]
    const float* prob = (const float*)d_in[1];   // [8,1,4000,1]

    compact_kernel<<<NB, 256>>>(prob);
    normalize_kernel<<<(NB * NN + 255) / 256, 256>>>(feat);
    dim3 grid(2 * JT63, (NN + TI - 1) / TI, NB);   // (mode|jt, it, b)
    mma_loss_kernel<<<grid, 256>>>();
    finalize_kernel<<<1, 32>>>((float*)d_out);
}

// round 7
// speedup vs baseline: 1.4989x; 1.1558x over previous
#include <cuda_runtime.h>
#include <cuda_bf16.h>
#include <stdint.h>
#include <math.h>

#define NB 8
#define NC 64
#define NN 4000
#define TI 128          // i-tile
#define TJ 64           // j-tile
#define JT63 63         // ceil(4000/64) j-tiles per mode
#define SMSTRIDE 72     // 64 bf16 + 8 pad (144B rows; 16B-aligned; ldmatrix conflict-free)

// Scratch (device globals; no allocations allowed)
__device__ __nv_bfloat16 g_feat2[NB * NN * NC];  // normalized, COMPACTED order:
                                                 // rows [0,nI) normal, [nI,NN) anomaly
__device__ int           g_pmap[NB * NN];        // orig idx -> p (normal) or ~pA (anomaly)
__device__ int           g_cnt[NB];
__device__ double        g_pos[NB];
__device__ double        g_neg[NB];

// ---------------------------------------------------------------------------
// Kernel 1: classify + build position map (deterministic), init accumulators.
// ---------------------------------------------------------------------------
__global__ void compact_kernel(const float* __restrict__ prob) {
    int b = blockIdx.x;
    int tid = threadIdx.x;
    __shared__ int wtN[8], wtA[8];
    __shared__ int baseN, baseA;
    if (tid == 0) { baseN = 0; baseA = 0; }
    __syncthreads();

    for (int c0 = 0; c0 < NN; c0 += 256) {
        int idx = c0 + tid;
        bool inr = idx < NN;
        bool nrm = false;
        if (inr) nrm = prob[b * NN + idx] < 0.5f;
        bool ano = inr && !nrm;
        unsigned mN = __ballot_sync(0xffffffffu, nrm);
        unsigned mA = __ballot_sync(0xffffffffu, ano);
        int lane = tid & 31, wid = tid >> 5;
        unsigned below = (1u << lane) - 1u;
        int pN = __popc(mN & below), pA = __popc(mA & below);
        if (lane == 0) { wtN[wid] = __popc(mN); wtA[wid] = __popc(mA); }
        __syncthreads();
        int oN = 0, oA = 0, tN = 0, tA = 0;
        for (int w = 0; w < 8; w++) {
            if (w < wid) { oN += wtN[w]; oA += wtA[w]; }
            tN += wtN[w]; tA += wtA[w];
        }
        if (nrm) g_pmap[b * NN + idx] = baseN + oN + pN;
        if (ano) g_pmap[b * NN + idx] = ~(baseA + oA + pA);
        __syncthreads();
        if (tid == 0) { baseN += tN; baseA += tA; }
        __syncthreads();
    }
    if (tid == 0) {
        g_cnt[b] = baseN;
        g_pos[b] = 0.0;
        g_neg[b] = 0.0;
    }
}

// ---------------------------------------------------------------------------
// Kernel 2: row-normalize (fp32) -> bf16, writing to COMPACTED row position.
// ---------------------------------------------------------------------------
__global__ void normalize_kernel(const float* __restrict__ feat) {
    int row = blockIdx.x * blockDim.x + threadIdx.x;
    if (row >= NB * NN) return;
    int b = row / NN;
    int n = row - b * NN;
    const float* src = feat + (size_t)b * NC * NN + n;
    float v[NC];
    float ss = 0.f;
#pragma unroll
    for (int c = 0; c < NC; c++) {
        float x = src[(size_t)c * NN];
        v[c] = x;
        ss += x * x;
    }
    float inv = 1.0f / fmaxf(sqrtf(ss), 1e-12f);
    int pm = g_pmap[b * NN + n];
    int dstRow = (pm >= 0) ? pm : (g_cnt[b] + ~pm);
    __nv_bfloat16* dst = g_feat2 + ((size_t)b * NN + dstRow) * NC;
#pragma unroll
    for (int c = 0; c < NC; c++) dst[c] = __float2bfloat16(v[c] * inv);
}

// ---------------------------------------------------------------------------
// Merged fused GEMM + loss.
// mode 0: normal x normal, UPPER TRIANGLE ONLY (cj > ri), sum exp, x2 at end.
// mode 1: normal x anomaly (softplus).
// Tile 128x64, 8 warps in M, warp tile 16x64. cp.async tile fills.
// ---------------------------------------------------------------------------
__device__ __forceinline__ void cpa16(unsigned dst, const void* src, bool valid) {
    int sz = valid ? 16 : 0;
    asm volatile("cp.async.cg.shared.global [%0], [%1], 16, %2;\n"
                 :: "r"(dst), "l"(src), "r"(sz));
}
__device__ __forceinline__ void ldm_x4(unsigned r[4], unsigned addr) {
    asm volatile("ldmatrix.sync.aligned.m8n8.x4.shared.b16 {%0,%1,%2,%3}, [%4];\n"
                 : "=r"(r[0]), "=r"(r[1]), "=r"(r[2]), "=r"(r[3]) : "r"(addr));
}
__device__ __forceinline__ void mma_bf16(float d[4], const unsigned a[4],
                                         unsigned b0, unsigned b1) {
    asm volatile(
        "mma.sync.aligned.m16n8k16.row.col.f32.bf16.bf16.f32 "
        "{%0,%1,%2,%3}, {%4,%5,%6,%7}, {%8,%9}, {%0,%1,%2,%3};\n"
        : "+f"(d[0]), "+f"(d[1]), "+f"(d[2]), "+f"(d[3])
        : "r"(a[0]), "r"(a[1]), "r"(a[2]), "r"(a[3]), "r"(b0), "r"(b1));
}

__global__ __launch_bounds__(256, 3) void mma_loss_kernel() {
    int b = blockIdx.z;
    int nI = g_cnt[b];
    int mode = (blockIdx.x >= JT63) ? 1 : 0;
    int jt = blockIdx.x - mode * JT63;
    int nJ = mode ? (NN - nI) : nI;
    int i0 = blockIdx.y * TI;
    int j0 = jt * TJ;
    if (i0 >= nI || j0 >= nJ) return;
    // mode 0: only tiles intersecting the strict upper triangle (cj > ri).
    if (mode == 0 && (j0 + TJ - 1) <= i0) return;

    __shared__ __nv_bfloat16 As[TI][SMSTRIDE];
    __shared__ __nv_bfloat16 Bs[TJ][SMSTRIDE];
    __shared__ float s_warp[8];

    int tid = threadIdx.x;
    const __nv_bfloat16* Abase = g_feat2 + ((size_t)b * NN + i0) * NC;
    const __nv_bfloat16* Bbase =
        g_feat2 + ((size_t)b * NN + (mode ? nI : 0) + j0) * NC;

    // cp.async tile fills: A = 1024 16B chunks (4/thread), B = 512 (2/thread).
#pragma unroll
    for (int c = 0; c < 4; c++) {
        int chunk = tid + c * 256;
        int r = chunk >> 3, col = chunk & 7;
        unsigned dst = (unsigned)__cvta_generic_to_shared(&As[r][col * 8]);
        cpa16(dst, Abase + (size_t)r * NC + col * 8, (i0 + r) < nI);
    }
#pragma unroll
    for (int c = 0; c < 2; c++) {
        int chunk = tid + c * 256;
        int r = chunk >> 3, col = chunk & 7;
        unsigned dst = (unsigned)__cvta_generic_to_shared(&Bs[r][col * 8]);
        cpa16(dst, Bbase + (size_t)r * NC + col * 8, (j0 + r) < nJ);
    }
    asm volatile("cp.async.commit_group;\n");
    asm volatile("cp.async.wait_group 0;\n");
    __syncthreads();

    int warp = tid >> 5, lane = tid & 31;
    int mBase = warp * 16;               // warp tile 16 (M) x 64 (N)

    float acc[8][4];
#pragma unroll
    for (int ni = 0; ni < 8; ni++)
#pragma unroll
        for (int e = 0; e < 4; e++) acc[ni][e] = 0.f;

#pragma unroll
    for (int ks = 0; ks < 4; ks++) {
        int k0 = ks * 16;
        unsigned afr[4];
        {
            unsigned a = (unsigned)__cvta_generic_to_shared(
                &As[mBase + (lane & 15)][k0 + (lane >> 4) * 8]);
            ldm_x4(afr, a);
        }
#pragma unroll
        for (int np = 0; np < 4; np++) {
            unsigned bt[4];
            unsigned a = (unsigned)__cvta_generic_to_shared(
                &Bs[np * 16 + (lane & 7) + 8 * (lane >> 4)]
                   [k0 + ((lane >> 3) & 1) * 8]);
            ldm_x4(bt, a);
            mma_bf16(acc[np * 2 + 0], afr, bt[0], bt[1]);
            mma_bf16(acc[np * 2 + 1], afr, bt[2], bt[3]);
        }
    }

    // Fused epilogue. sim = dot*10; exp(sim) = exp2(dot*10*log2e).
    // mode 0: sum exp(sim) over cj > ri only (x2 applied at the atomic).
    // mode 1: sum log2(1+exp(sim)); * ln2 at the atomic (eps ~3e-6 rel, dropped).
    const float K10LOG2E = 14.4269504089f;
    int g = lane >> 2, tq = lane & 3;
    int riB = i0 + mBase + g;
    int cjB = j0 + tq * 2;
    float sumv = 0.f;
#pragma unroll
    for (int ni = 0; ni < 8; ni++) {
#pragma unroll
        for (int e = 0; e < 4; e++) {
            int ri = riB + ((e >> 1) ? 8 : 0);
            int cj = cjB + ni * 8 + (e & 1);
            if (ri >= nI || cj >= nJ) continue;
            if (mode == 0) {
                if (cj > ri) sumv += exp2f(acc[ni][e] * K10LOG2E);
            } else {
                float ex = exp2f(acc[ni][e] * K10LOG2E);
                sumv += __log2f(1.0f + ex);
            }
        }
    }

#pragma unroll
    for (int o = 16; o; o >>= 1)
        sumv += __shfl_down_sync(0xffffffffu, sumv, o);
    if (lane == 0) s_warp[warp] = sumv;
    __syncthreads();
    if (warp == 0) {
        float v = (lane < 8) ? s_warp[lane] : 0.f;
#pragma unroll
        for (int o = 4; o; o >>= 1)
            v += __shfl_down_sync(0xffffffffu, v, o);
        if (lane == 0) {
            if (mode == 0) atomicAdd(&g_pos[b], 2.0 * (double)v);  // symmetry
            else atomicAdd(&g_neg[b], (double)v * 0.6931471805599453);  // ln2
        }
    }
}

// ---------------------------------------------------------------------------
// Finalize scalar
// ---------------------------------------------------------------------------
__global__ void finalize_kernel(float* __restrict__ out) {
    int tid = threadIdx.x;
    double per = 0.0, vcnt = 0.0;
    if (tid < NB) {
        int nn = g_cnt[tid];
        int na = NN - nn;
        bool valid = (nn >= 10) && (na >= 5);
        double pc = (double)nn * (double)nn - (double)nn;
        double cc = (double)nn * (double)na;
        double pm = g_pos[tid] / (pc > 1.0 ? pc : 1.0);
        double pl = -log(pm + 1e-6);
        double nl = g_neg[tid] / (cc > 1.0 ? cc : 1.0);
        if (valid) { per = pl + nl; vcnt = 1.0; }
    }
    for (int o = 16; o; o >>= 1) {
        per += __shfl_down_sync(0xffffffffu, per, o);
        vcnt += __shfl_down_sync(0xffffffffu, vcnt, o);
    }
    if (tid == 0) out[0] = (float)(per / (vcnt > 1.0 ? vcnt : 1.0));
}

extern "C" void kernel_launch(void* const* d_in, const int* in_sizes, int n_in,
                              void* d_out, int out_size) {
    const float* feat = (const float*)d_in[0];   // [8,64,4000,1]
    const float* prob = (const float*)d_in[1];   // [8,1,4000,1]

    compact_kernel<<<NB, 256>>>(prob);
    normalize_kernel<<<(NB * NN + 255) / 256, 256>>>(feat);
    dim3 grid(2 * JT63, (NN + TI - 1) / TI, NB);   // (mode|jt, it, b)
    mma_loss_kernel<<<grid, 256>>>();
    finalize_kernel<<<1, 32>>>((float*)d_out);
}